// round 14
// baseline (speedup 1.0000x reference)
#include <cuda_runtime.h>
#include <cstdint>

#define Hh 576
#define Ww 640
#define HW (Hh*Ww)
#define BIGF 1e10f
#define EPSF 1e-5f

// ---- scratch (__device__ globals; zero-initialized at module load) ----
// Depth keys: key = ~bits(z); z>0 => key>0x80000000; key==0 means empty.
// min(z) = decode(max key). k_final resets keys to 0 (pure stores) => replay invariant.
__device__ unsigned int g_depth_key[HW];
__device__ float        g_patchmin[HW];
__device__ float4       g_acc4[HW];

__device__ __forceinline__ void red_add_v4(float4* p, float a, float b, float c, float d) {
    asm volatile("red.global.add.v4.f32 [%0], {%1,%2,%3,%4};"
                 :: "l"(__cvta_generic_to_global(p)),
                    "f"(a), "f"(b), "f"(c), "f"(d) : "memory");
}
__device__ __forceinline__ void red_add_f32(float* p, float v) {
    asm volatile("red.global.add.f32 [%0], %1;"
                 :: "l"(__cvta_generic_to_global(p)), "f"(v) : "memory");
}

// stage this block's 256 points (768 floats) into smem, coalesced.
// full blocks: 192 float4 loads (pts + 768*blockIdx.x is 16B aligned).
// partial last block: scalar fallback.
__device__ __forceinline__ void stage_pts(float* sp, const float* __restrict__ pts,
                                          int b0, int n, int tid) {
    int cnt = min(256, n - b0);
    if (cnt == 256) {
        const float4* g = reinterpret_cast<const float4*>(pts) + 192 * blockIdx.x;
        if (tid < 192) reinterpret_cast<float4*>(sp)[tid] = g[tid];
    } else {
        for (int k = tid; k < cnt * 3; k += 256) sp[k] = pts[3 * b0 + k];
    }
    __syncthreads();
}

// ---- k1: z-buffer scatter-min (complement-key atomicMax), smem-staged pts ----
__global__ void __launch_bounds__(256) k_zmin(const float* __restrict__ pts,
                                              const int* __restrict__ mask, int n) {
    __shared__ float sp[768];
    int tid = threadIdx.x;
    int b0 = blockIdx.x * 256;
    stage_pts(sp, pts, b0, n, tid);

    int i = b0 + tid;
    if (i >= n) return;
    float x = sp[3*tid], y = sp[3*tid+1], z = sp[3*tid+2];
    int px = __float2int_rd(x), py = __float2int_rd(y);
    bool valid = (px >= 0) & (px < Ww) & (py >= 0) & (py < Hh) & (mask[i] > 0);
    if (valid)
        atomicMax(&g_depth_key[py * Ww + px], ~__float_as_uint(z));
}

// ---- k2: 5x5 patch-min (smem key-max) + depth output + accumulator zeroing ----
#define TW 32
#define TH 8
#define SW (TW + 4)
#define SH (TH + 4)
__global__ void k_patchmin(float* __restrict__ out_weight,
                           float* __restrict__ out_depth) {
    __shared__ unsigned int tile[SH * SW];
    int tid = threadIdx.x;
    int bx = blockIdx.x % (Ww / TW);
    int by = blockIdx.x / (Ww / TW);
    int x0 = bx * TW, y0 = by * TH;

    #pragma unroll
    for (int k = tid; k < SH * SW; k += 256) {
        int ly = k / SW, lx = k % SW;
        int gy = y0 + ly - 2, gx = x0 + lx - 2;
        unsigned v = 0u;  // empty (BIG depth)
        if (gy >= 0 && gy < Hh && gx >= 0 && gx < Ww)
            v = g_depth_key[gy * Ww + gx];
        tile[k] = v;
    }
    __syncthreads();

    int tx = tid % TW, ty = tid / TW;
    unsigned m = 0u;
    #pragma unroll
    for (int dy = 0; dy < 5; ++dy) {
        #pragma unroll
        for (int dx = 0; dx < 5; ++dx)
            m = max(m, tile[(ty + dy) * SW + (tx + dx)]);
    }
    int gi = (y0 + ty) * Ww + (x0 + tx);
    g_patchmin[gi] = (m == 0u) ? BIGF : __uint_as_float(~m);

    unsigned ck = tile[(ty + 2) * SW + (tx + 2)];
    out_depth[gi] = ck ? __uint_as_float(~ck) : 0.f;

    g_acc4[gi] = make_float4(0.f, 0.f, 0.f, 0.f);
    out_weight[gi] = 0.f;
}

// ---- k3: visibility + warp-cooperative 7x7 splat (smem-staged pts) ----
__global__ void __launch_bounds__(256) k_splat(
                        const float* __restrict__ pts,
                        const float* __restrict__ color,
                        const float* __restrict__ imw,
                        const int*   __restrict__ mask,
                        const float* __restrict__ thresh,
                        float* __restrict__ out_weight,
                        float* __restrict__ out_vis,
                        int n) {
    __shared__ float sp[768];
    int tid = threadIdx.x;
    int b0 = blockIdx.x * 256;
    stage_pts(sp, pts, b0, n, tid);

    int i = b0 + tid;
    int lane = tid & 31;
    int wloc = tid - lane;                 // warp's local base within block

    // per-lane constant splat offsets: update u covers (oy,ox) = (u/7-3, u%7-3)
    int u1 = lane + 32;
    int ox0 = lane % 7 - 3, oy0 = lane / 7 - 3;
    int ox1 = u1 % 7 - 3,   oy1 = u1 / 7 - 3;
    float cxo0 = (float)ox0 + 0.5f, cyo0 = (float)oy0 + 0.5f;
    float cxo1 = (float)ox1 + 0.5f, cyo1 = (float)oy1 + 0.5f;
    int ioff0 = oy0 * Ww + ox0;
    int ioff1 = oy1 * Ww + ox1;
    bool has1 = (u1 < 49);

    bool vis = false;
    if (i < n) {
        float x = sp[3*tid], y = sp[3*tid+1], z = sp[3*tid+2];
        int px = __float2int_rd(x), py = __float2int_rd(y);
        bool valid = (px >= 0) & (px < Ww) & (py >= 0) & (py < Hh) & (mask[i] > 0);
        int ccx = min(max(px, 0), Ww - 1);
        int ccy = min(max(py, 0), Hh - 1);
        float pm = g_patchmin[ccy * Ww + ccx];
        float th = __ldg(thresh);
        vis = valid && (z <= pm + th);
        out_vis[i] = vis ? 1.0f : 0.0f;
    }

    unsigned vm = __ballot_sync(0xffffffffu, vis);
    while (vm) {
        int src = __ffs(vm) - 1;
        vm &= vm - 1;
        int l = wloc + src;                   // local index -> smem broadcast reads
        int j = b0 + l;                       // global index for color/imw
        float xx = sp[3*l];
        float yy = sp[3*l+1];
        float s0 = __ldg(&color[3*j]);
        float s1 = __ldg(&color[3*j+1]);
        float s2 = __ldg(&color[3*j+2]);
        float swv = __ldg(&imw[j]);
        int pxb = __float2int_rd(xx);
        int pyb = __float2int_rd(yy);
        float fx = (float)pxb - xx;
        float fy = (float)pyb - yy;
        int base = pyb * Ww + pxb;

        {
            int sx = pxb + ox0, sy = pyb + oy0;
            if (((unsigned)sx < Ww) & ((unsigned)sy < Hh)) {
                float dx = fx + cxo0, dy = fy + cyo0;
                float w = __fdividef(1.0f, fmaf(dx, dx, fmaf(dy, dy, EPSF)));
                int idx = base + ioff0;
                red_add_v4(&g_acc4[idx], w * s0, w * s1, w * s2, w * swv);
                red_add_f32(&out_weight[idx], w);
            }
        }
        if (has1) {
            int sx = pxb + ox1, sy = pyb + oy1;
            if (((unsigned)sx < Ww) & ((unsigned)sy < Hh)) {
                float dx = fx + cxo1, dy = fy + cyo1;
                float w = __fdividef(1.0f, fmaf(dx, dx, fmaf(dy, dy, EPSF)));
                int idx = base + ioff1;
                red_add_v4(&g_acc4[idx], w * s0, w * s1, w * s2, w * swv);
                red_add_f32(&out_weight[idx], w);
            }
        }
    }
}

// ---- k4: acc4 -> color/imw. Block=64 threads, 4 px/thread (MLP=4), grid=1440.
//      Color staged in smem for coalesced float4 stores; key reset = pure stores. ----
#define FB 64
__global__ void __launch_bounds__(FB) k_final(float* __restrict__ out_color,
                                              float* __restrict__ out_imw) {
    __shared__ float sc[256 * 3];
    int tid = threadIdx.x;
    int base = blockIdx.x * 256;

    float4 a0 = __ldcg(&g_acc4[base + tid]);
    float4 a1 = __ldcg(&g_acc4[base + tid + 64]);
    float4 a2 = __ldcg(&g_acc4[base + tid + 128]);
    float4 a3 = __ldcg(&g_acc4[base + tid + 192]);

    sc[(tid      ) * 3 + 0] = a0.x; sc[(tid      ) * 3 + 1] = a0.y; sc[(tid      ) * 3 + 2] = a0.z;
    sc[(tid +  64) * 3 + 0] = a1.x; sc[(tid +  64) * 3 + 1] = a1.y; sc[(tid +  64) * 3 + 2] = a1.z;
    sc[(tid + 128) * 3 + 0] = a2.x; sc[(tid + 128) * 3 + 1] = a2.y; sc[(tid + 128) * 3 + 2] = a2.z;
    sc[(tid + 192) * 3 + 0] = a3.x; sc[(tid + 192) * 3 + 1] = a3.y; sc[(tid + 192) * 3 + 2] = a3.z;

    out_imw[base + tid]       = a0.w;
    out_imw[base + tid +  64] = a1.w;
    out_imw[base + tid + 128] = a2.w;
    out_imw[base + tid + 192] = a3.w;

    g_depth_key[base + tid]       = 0u;   // reset for next replay
    g_depth_key[base + tid +  64] = 0u;
    g_depth_key[base + tid + 128] = 0u;
    g_depth_key[base + tid + 192] = 0u;

    __syncthreads();
    float4* oc = reinterpret_cast<float4*>(out_color) + blockIdx.x * 192;
    const float4* s4 = reinterpret_cast<const float4*>(sc);
    oc[tid]       = s4[tid];
    oc[tid +  64] = s4[tid + 64];
    oc[tid + 128] = s4[tid + 128];
}

extern "C" void kernel_launch(void* const* d_in, const int* in_sizes, int n_in,
                              void* d_out, int out_size) {
    const float* pts    = (const float*)d_in[0];
    const float* color  = (const float*)d_in[1];
    const float* imw    = (const float*)d_in[2];
    const int*   mask   = (const int*)  d_in[3];
    const float* thresh = (const float*)d_in[4];
    int n = in_sizes[3];

    float* out = (float*)d_out;
    float* out_depth  = out;
    float* out_color  = out + HW;
    float* out_imw    = out + HW * 4;
    float* out_weight = out + HW * 5;
    float* out_vis    = out + HW * 6;

    const int BT = 256;
    int gp  = (n + BT - 1) / BT;          // 782
    int gt  = (Ww / TW) * (Hh / TH);      // 1440
    int gf  = HW / 256;                   // 1440 blocks of 64 threads

    k_zmin<<<gp, BT>>>(pts, mask, n);
    k_patchmin<<<gt, BT>>>(out_weight, out_depth);
    k_splat<<<gp, BT>>>(pts, color, imw, mask, thresh, out_weight, out_vis, n);
    k_final<<<gf, FB>>>(out_color, out_imw);
}

// round 15
// speedup vs baseline: 1.0312x; 1.0312x over previous
#include <cuda_runtime.h>
#include <cstdint>

#define Hh 576
#define Ww 640
#define HW (Hh*Ww)
#define BIGF 1e10f
#define EPSF 1e-5f

// ---- scratch (__device__ globals; zero-initialized at module load) ----
// Depth keys: key = ~bits(z); z>0 => key>0x80000000; key==0 means empty.
// min(z) = decode(max key). k_final resets keys to 0 (pure stores) => replay invariant.
__device__ unsigned int g_depth_key[HW];
__device__ float        g_patchmin[HW];
__device__ float4       g_acc4[HW];

__device__ __forceinline__ void red_add_v4(float4* p, float a, float b, float c, float d) {
    asm volatile("red.global.add.v4.f32 [%0], {%1,%2,%3,%4};"
                 :: "l"(__cvta_generic_to_global(p)),
                    "f"(a), "f"(b), "f"(c), "f"(d) : "memory");
}
__device__ __forceinline__ void red_add_f32(float* p, float v) {
    asm volatile("red.global.add.f32 [%0], %1;"
                 :: "l"(__cvta_generic_to_global(p)), "f"(v) : "memory");
}

// ---- k1: z-buffer scatter-min (complement-key atomicMax), 1 pt/thread ----
__global__ void k_zmin(const float* __restrict__ pts, const int* __restrict__ mask, int n) {
    int i = blockIdx.x * blockDim.x + threadIdx.x;
    if (i >= n) return;
    float x = __ldg(&pts[3*i]), y = __ldg(&pts[3*i+1]), z = __ldg(&pts[3*i+2]);
    int px = __float2int_rd(x), py = __float2int_rd(y);
    bool valid = (px >= 0) & (px < Ww) & (py >= 0) & (py < Hh) & (mask[i] > 0);
    if (valid)
        atomicMax(&g_depth_key[py * Ww + px], ~__float_as_uint(z));
}

// ---- k2: 5x5 patch-min (smem key-max) + depth output + accumulator zeroing ----
#define TW 32
#define TH 8
#define SW (TW + 4)
#define SH (TH + 4)
__global__ void k_patchmin(float* __restrict__ out_weight,
                           float* __restrict__ out_depth) {
    __shared__ unsigned int tile[SH * SW];
    int tid = threadIdx.x;
    int bx = blockIdx.x % (Ww / TW);
    int by = blockIdx.x / (Ww / TW);
    int x0 = bx * TW, y0 = by * TH;

    #pragma unroll
    for (int k = tid; k < SH * SW; k += 256) {
        int ly = k / SW, lx = k % SW;
        int gy = y0 + ly - 2, gx = x0 + lx - 2;
        unsigned v = 0u;  // empty (BIG depth)
        if (gy >= 0 && gy < Hh && gx >= 0 && gx < Ww)
            v = g_depth_key[gy * Ww + gx];
        tile[k] = v;
    }
    __syncthreads();

    int tx = tid % TW, ty = tid / TW;
    unsigned m = 0u;
    #pragma unroll
    for (int dy = 0; dy < 5; ++dy) {
        #pragma unroll
        for (int dx = 0; dx < 5; ++dx)
            m = max(m, tile[(ty + dy) * SW + (tx + dx)]);
    }
    int gi = (y0 + ty) * Ww + (x0 + tx);
    g_patchmin[gi] = (m == 0u) ? BIGF : __uint_as_float(~m);

    unsigned ck = tile[(ty + 2) * SW + (tx + 2)];
    out_depth[gi] = ck ? __uint_as_float(~ck) : 0.f;

    g_acc4[gi] = make_float4(0.f, 0.f, 0.f, 0.f);
    out_weight[gi] = 0.f;
}

// ---- k3: visibility + warp-cooperative 7x7 splat (uniform-load broadcast) ----
__global__ void __launch_bounds__(256) k_splat(
                        const float* __restrict__ pts,
                        const float* __restrict__ color,
                        const float* __restrict__ imw,
                        const int*   __restrict__ mask,
                        const float* __restrict__ thresh,
                        float* __restrict__ out_weight,
                        float* __restrict__ out_vis,
                        int n) {
    int i = blockIdx.x * blockDim.x + threadIdx.x;
    int lane = threadIdx.x & 31;
    int warp_base = i - lane;

    // per-lane constant splat offsets: update u covers (oy,ox) = (u/7-3, u%7-3)
    int u1 = lane + 32;
    int ox0 = lane % 7 - 3, oy0 = lane / 7 - 3;
    int ox1 = u1 % 7 - 3,   oy1 = u1 / 7 - 3;
    float cxo0 = (float)ox0 + 0.5f, cyo0 = (float)oy0 + 0.5f;
    float cxo1 = (float)ox1 + 0.5f, cyo1 = (float)oy1 + 0.5f;
    int ioff0 = oy0 * Ww + ox0;
    int ioff1 = oy1 * Ww + ox1;
    bool has1 = (u1 < 49);

    bool vis = false;
    if (i < n) {
        float x = pts[3*i], y = pts[3*i+1], z = pts[3*i+2];
        int px = __float2int_rd(x), py = __float2int_rd(y);
        bool valid = (px >= 0) & (px < Ww) & (py >= 0) & (py < Hh) & (mask[i] > 0);
        int ccx = min(max(px, 0), Ww - 1);
        int ccy = min(max(py, 0), Hh - 1);
        float pm = g_patchmin[ccy * Ww + ccx];
        float th = __ldg(thresh);
        vis = valid && (z <= pm + th);
        out_vis[i] = vis ? 1.0f : 0.0f;
    }

    unsigned vm = __ballot_sync(0xffffffffu, vis);
    while (vm) {
        int src = __ffs(vm) - 1;
        vm &= vm - 1;
        int j = warp_base + src;              // warp-uniform -> broadcast loads
        float xx = __ldg(&pts[3*j]);
        float yy = __ldg(&pts[3*j+1]);
        float s0 = __ldg(&color[3*j]);
        float s1 = __ldg(&color[3*j+1]);
        float s2 = __ldg(&color[3*j+2]);
        float swv = __ldg(&imw[j]);
        int pxb = __float2int_rd(xx);
        int pyb = __float2int_rd(yy);
        float fx = (float)pxb - xx;
        float fy = (float)pyb - yy;
        int base = pyb * Ww + pxb;

        {
            int sx = pxb + ox0, sy = pyb + oy0;
            if (((unsigned)sx < Ww) & ((unsigned)sy < Hh)) {
                float dx = fx + cxo0, dy = fy + cyo0;
                float w = __fdividef(1.0f, fmaf(dx, dx, fmaf(dy, dy, EPSF)));
                int idx = base + ioff0;
                red_add_v4(&g_acc4[idx], w * s0, w * s1, w * s2, w * swv);
                red_add_f32(&out_weight[idx], w);
            }
        }
        if (has1) {
            int sx = pxb + ox1, sy = pyb + oy1;
            if (((unsigned)sx < Ww) & ((unsigned)sy < Hh)) {
                float dx = fx + cxo1, dy = fy + cyo1;
                float w = __fdividef(1.0f, fmaf(dx, dx, fmaf(dy, dy, EPSF)));
                int idx = base + ioff1;
                red_add_v4(&g_acc4[idx], w * s0, w * s1, w * s2, w * swv);
                red_add_f32(&out_weight[idx], w);
            }
        }
    }
}

// ---- k4: acc4 -> color/imw. Block=64 threads, 4 px/thread (MLP=4), grid=1440.
//      Block covers 256 contiguous pixels; color staged in smem for coalesced
//      float4 stores. Depth-key reset = pure stores (replay invariant). ----
#define FB 64
__global__ void __launch_bounds__(FB) k_final(float* __restrict__ out_color,
                                              float* __restrict__ out_imw) {
    __shared__ float sc[256 * 3];
    int tid = threadIdx.x;
    int base = blockIdx.x * 256;

    // 4 independent 16B loads issued back-to-back (MLP=4), coalesced per warp
    float4 a0 = __ldcg(&g_acc4[base + tid]);
    float4 a1 = __ldcg(&g_acc4[base + tid + 64]);
    float4 a2 = __ldcg(&g_acc4[base + tid + 128]);
    float4 a3 = __ldcg(&g_acc4[base + tid + 192]);

    sc[(tid      ) * 3 + 0] = a0.x; sc[(tid      ) * 3 + 1] = a0.y; sc[(tid      ) * 3 + 2] = a0.z;
    sc[(tid +  64) * 3 + 0] = a1.x; sc[(tid +  64) * 3 + 1] = a1.y; sc[(tid +  64) * 3 + 2] = a1.z;
    sc[(tid + 128) * 3 + 0] = a2.x; sc[(tid + 128) * 3 + 1] = a2.y; sc[(tid + 128) * 3 + 2] = a2.z;
    sc[(tid + 192) * 3 + 0] = a3.x; sc[(tid + 192) * 3 + 1] = a3.y; sc[(tid + 192) * 3 + 2] = a3.z;

    out_imw[base + tid]       = a0.w;
    out_imw[base + tid +  64] = a1.w;
    out_imw[base + tid + 128] = a2.w;
    out_imw[base + tid + 192] = a3.w;

    // reset depth keys for next replay (pure stores, coalesced)
    g_depth_key[base + tid]       = 0u;
    g_depth_key[base + tid +  64] = 0u;
    g_depth_key[base + tid + 128] = 0u;
    g_depth_key[base + tid + 192] = 0u;

    __syncthreads();
    float4* oc = reinterpret_cast<float4*>(out_color) + blockIdx.x * 192;
    const float4* s4 = reinterpret_cast<const float4*>(sc);
    oc[tid]       = s4[tid];
    oc[tid +  64] = s4[tid + 64];
    oc[tid + 128] = s4[tid + 128];
}

extern "C" void kernel_launch(void* const* d_in, const int* in_sizes, int n_in,
                              void* d_out, int out_size) {
    const float* pts    = (const float*)d_in[0];
    const float* color  = (const float*)d_in[1];
    const float* imw    = (const float*)d_in[2];
    const int*   mask   = (const int*)  d_in[3];
    const float* thresh = (const float*)d_in[4];
    int n = in_sizes[3];

    float* out = (float*)d_out;
    float* out_depth  = out;
    float* out_color  = out + HW;
    float* out_imw    = out + HW * 4;
    float* out_weight = out + HW * 5;
    float* out_vis    = out + HW * 6;

    const int BT = 256;
    int gp  = (n + BT - 1) / BT;          // 782
    int gt  = (Ww / TW) * (Hh / TH);      // 1440
    int gf  = HW / 256;                   // 1440 blocks of 64 threads

    k_zmin<<<gp, BT>>>(pts, mask, n);
    k_patchmin<<<gt, BT>>>(out_weight, out_depth);
    k_splat<<<gp, BT>>>(pts, color, imw, mask, thresh, out_weight, out_vis, n);
    k_final<<<gf, FB>>>(out_color, out_imw);
}

// round 16
// speedup vs baseline: 1.1182x; 1.0845x over previous
#include <cuda_runtime.h>
#include <cstdint>

#define Hh 576
#define Ww 640
#define HW (Hh*Ww)
#define BIGF 1e10f
#define EPSF 1e-5f

// ---- scratch (__device__ globals; zero-initialized at module load) ----
// Depth keys: key = ~bits(z); z>0 => key>0x80000000; key==0 means empty.
// min(z) = decode(max key). k_final resets keys to 0 (pure stores) => replay invariant.
__device__ unsigned int g_depth_key[HW];
__device__ float        g_patchmin[HW];
__device__ float4       g_acc4[HW];

__device__ __forceinline__ void red_add_v4(float4* p, float a, float b, float c, float d) {
    asm volatile("red.global.add.v4.f32 [%0], {%1,%2,%3,%4};"
                 :: "l"(__cvta_generic_to_global(p)),
                    "f"(a), "f"(b), "f"(c), "f"(d) : "memory");
}
__device__ __forceinline__ void red_add_f32(float* p, float v) {
    asm volatile("red.global.add.f32 [%0], %1;"
                 :: "l"(__cvta_generic_to_global(p)), "f"(v) : "memory");
}

// ---- k1: z-buffer scatter-min (complement-key atomicMax), 1 pt/thread ----
__global__ void k_zmin(const float* __restrict__ pts, const int* __restrict__ mask, int n) {
    int i = blockIdx.x * blockDim.x + threadIdx.x;
    if (i >= n) return;
    float x = __ldg(&pts[3*i]), y = __ldg(&pts[3*i+1]), z = __ldg(&pts[3*i+2]);
    int px = __float2int_rd(x), py = __float2int_rd(y);
    bool valid = (px >= 0) & (px < Ww) & (py >= 0) & (py < Hh) & (mask[i] > 0);
    if (valid)
        atomicMax(&g_depth_key[py * Ww + px], ~__float_as_uint(z));
}

// ---- k2: 5x5 patch-min (smem key-max) + depth output + accumulator zeroing ----
#define TW 32
#define TH 8
#define SW (TW + 4)
#define SH (TH + 4)
__global__ void k_patchmin(float* __restrict__ out_weight,
                           float* __restrict__ out_depth) {
    __shared__ unsigned int tile[SH * SW];
    int tid = threadIdx.x;
    int bx = blockIdx.x % (Ww / TW);
    int by = blockIdx.x / (Ww / TW);
    int x0 = bx * TW, y0 = by * TH;

    #pragma unroll
    for (int k = tid; k < SH * SW; k += 256) {
        int ly = k / SW, lx = k % SW;
        int gy = y0 + ly - 2, gx = x0 + lx - 2;
        unsigned v = 0u;  // empty (BIG depth)
        if (gy >= 0 && gy < Hh && gx >= 0 && gx < Ww)
            v = g_depth_key[gy * Ww + gx];
        tile[k] = v;
    }
    __syncthreads();

    int tx = tid % TW, ty = tid / TW;
    unsigned m = 0u;
    #pragma unroll
    for (int dy = 0; dy < 5; ++dy) {
        #pragma unroll
        for (int dx = 0; dx < 5; ++dx)
            m = max(m, tile[(ty + dy) * SW + (tx + dx)]);
    }
    int gi = (y0 + ty) * Ww + (x0 + tx);
    g_patchmin[gi] = (m == 0u) ? BIGF : __uint_as_float(~m);

    unsigned ck = tile[(ty + 2) * SW + (tx + 2)];
    out_depth[gi] = ck ? __uint_as_float(~ck) : 0.f;

    g_acc4[gi] = make_float4(0.f, 0.f, 0.f, 0.f);
    out_weight[gi] = 0.f;
}

// ---- k3: visibility + warp-cooperative 7x7 splat (uniform-load broadcast) ----
__global__ void __launch_bounds__(256) k_splat(
                        const float* __restrict__ pts,
                        const float* __restrict__ color,
                        const float* __restrict__ imw,
                        const int*   __restrict__ mask,
                        const float* __restrict__ thresh,
                        float* __restrict__ out_weight,
                        float* __restrict__ out_vis,
                        int n) {
    int i = blockIdx.x * blockDim.x + threadIdx.x;
    int lane = threadIdx.x & 31;
    int warp_base = i - lane;

    // per-lane constant splat offsets: update u covers (oy,ox) = (u/7-3, u%7-3)
    int u1 = lane + 32;
    int ox0 = lane % 7 - 3, oy0 = lane / 7 - 3;
    int ox1 = u1 % 7 - 3,   oy1 = u1 / 7 - 3;
    float cxo0 = (float)ox0 + 0.5f, cyo0 = (float)oy0 + 0.5f;
    float cxo1 = (float)ox1 + 0.5f, cyo1 = (float)oy1 + 0.5f;
    int ioff0 = oy0 * Ww + ox0;
    int ioff1 = oy1 * Ww + ox1;
    bool has1 = (u1 < 49);

    bool vis = false;
    if (i < n) {
        float x = pts[3*i], y = pts[3*i+1], z = pts[3*i+2];
        int px = __float2int_rd(x), py = __float2int_rd(y);
        bool valid = (px >= 0) & (px < Ww) & (py >= 0) & (py < Hh) & (mask[i] > 0);
        int ccx = min(max(px, 0), Ww - 1);
        int ccy = min(max(py, 0), Hh - 1);
        float pm = g_patchmin[ccy * Ww + ccx];
        float th = __ldg(thresh);
        vis = valid && (z <= pm + th);
        out_vis[i] = vis ? 1.0f : 0.0f;
    }

    unsigned vm = __ballot_sync(0xffffffffu, vis);
    while (vm) {
        int src = __ffs(vm) - 1;
        vm &= vm - 1;
        int j = warp_base + src;              // warp-uniform -> broadcast loads
        float xx = __ldg(&pts[3*j]);
        float yy = __ldg(&pts[3*j+1]);
        float s0 = __ldg(&color[3*j]);
        float s1 = __ldg(&color[3*j+1]);
        float s2 = __ldg(&color[3*j+2]);
        float swv = __ldg(&imw[j]);
        int pxb = __float2int_rd(xx);
        int pyb = __float2int_rd(yy);
        float fx = (float)pxb - xx;
        float fy = (float)pyb - yy;
        int base = pyb * Ww + pxb;

        {
            int sx = pxb + ox0, sy = pyb + oy0;
            if (((unsigned)sx < Ww) & ((unsigned)sy < Hh)) {
                float dx = fx + cxo0, dy = fy + cyo0;
                float w = __fdividef(1.0f, fmaf(dx, dx, fmaf(dy, dy, EPSF)));
                int idx = base + ioff0;
                red_add_v4(&g_acc4[idx], w * s0, w * s1, w * s2, w * swv);
                red_add_f32(&out_weight[idx], w);
            }
        }
        if (has1) {
            int sx = pxb + ox1, sy = pyb + oy1;
            if (((unsigned)sx < Ww) & ((unsigned)sy < Hh)) {
                float dx = fx + cxo1, dy = fy + cyo1;
                float w = __fdividef(1.0f, fmaf(dx, dx, fmaf(dy, dy, EPSF)));
                int idx = base + ioff1;
                red_add_v4(&g_acc4[idx], w * s0, w * s1, w * s2, w * swv);
                red_add_f32(&out_weight[idx], w);
            }
        }
    }
}

// ---- k4: acc4 -> color/imw. Block=64 threads, 4 px/thread (MLP=4), grid=1440.
//      Block covers 256 contiguous pixels; color staged in smem for coalesced
//      float4 stores. Depth-key reset = pure stores (replay invariant). ----
#define FB 64
__global__ void __launch_bounds__(FB) k_final(float* __restrict__ out_color,
                                              float* __restrict__ out_imw) {
    __shared__ float sc[256 * 3];
    int tid = threadIdx.x;
    int base = blockIdx.x * 256;

    // 4 independent 16B loads issued back-to-back (MLP=4), coalesced per warp
    float4 a0 = __ldcg(&g_acc4[base + tid]);
    float4 a1 = __ldcg(&g_acc4[base + tid + 64]);
    float4 a2 = __ldcg(&g_acc4[base + tid + 128]);
    float4 a3 = __ldcg(&g_acc4[base + tid + 192]);

    sc[(tid      ) * 3 + 0] = a0.x; sc[(tid      ) * 3 + 1] = a0.y; sc[(tid      ) * 3 + 2] = a0.z;
    sc[(tid +  64) * 3 + 0] = a1.x; sc[(tid +  64) * 3 + 1] = a1.y; sc[(tid +  64) * 3 + 2] = a1.z;
    sc[(tid + 128) * 3 + 0] = a2.x; sc[(tid + 128) * 3 + 1] = a2.y; sc[(tid + 128) * 3 + 2] = a2.z;
    sc[(tid + 192) * 3 + 0] = a3.x; sc[(tid + 192) * 3 + 1] = a3.y; sc[(tid + 192) * 3 + 2] = a3.z;

    out_imw[base + tid]       = a0.w;
    out_imw[base + tid +  64] = a1.w;
    out_imw[base + tid + 128] = a2.w;
    out_imw[base + tid + 192] = a3.w;

    // reset depth keys for next replay (pure stores, coalesced)
    g_depth_key[base + tid]       = 0u;
    g_depth_key[base + tid +  64] = 0u;
    g_depth_key[base + tid + 128] = 0u;
    g_depth_key[base + tid + 192] = 0u;

    __syncthreads();
    float4* oc = reinterpret_cast<float4*>(out_color) + blockIdx.x * 192;
    const float4* s4 = reinterpret_cast<const float4*>(sc);
    oc[tid]       = s4[tid];
    oc[tid +  64] = s4[tid + 64];
    oc[tid + 128] = s4[tid + 128];
}

extern "C" void kernel_launch(void* const* d_in, const int* in_sizes, int n_in,
                              void* d_out, int out_size) {
    const float* pts    = (const float*)d_in[0];
    const float* color  = (const float*)d_in[1];
    const float* imw    = (const float*)d_in[2];
    const int*   mask   = (const int*)  d_in[3];
    const float* thresh = (const float*)d_in[4];
    int n = in_sizes[3];

    float* out = (float*)d_out;
    float* out_depth  = out;
    float* out_color  = out + HW;
    float* out_imw    = out + HW * 4;
    float* out_weight = out + HW * 5;
    float* out_vis    = out + HW * 6;

    const int BT = 256;
    int gp  = (n + BT - 1) / BT;          // 782
    int gt  = (Ww / TW) * (Hh / TH);      // 1440
    int gf  = HW / 256;                   // 1440 blocks of 64 threads

    k_zmin<<<gp, BT>>>(pts, mask, n);
    k_patchmin<<<gt, BT>>>(out_weight, out_depth);
    k_splat<<<gp, BT>>>(pts, color, imw, mask, thresh, out_weight, out_vis, n);
    k_final<<<gf, FB>>>(out_color, out_imw);
}